// round 2
// baseline (speedup 1.0000x reference)
#include <cuda_runtime.h>
#include <math.h>

// B=8, C=512, H=W=32 -> N=1024 tokens, 8 heads, d_k=64, inner=512
#define NB   8
#define NC   512
#define NN   1024
#define NH   8
#define DK   64
#define ITOT 1536
#define SCALE 0.125f

typedef unsigned long long u64t;

// Scratch (device globals; allocation-free rule)
static __device__ __align__(16) float g_q[(size_t)NB * NH * NN * DK];   // [B,H,N,64]
static __device__ __align__(16) float g_k[(size_t)NB * NH * NN * DK];
static __device__ __align__(16) float g_v[(size_t)NB * NH * NN * DK];
static __device__ __align__(16) float g_mid[(size_t)NB * NN * 512];     // [B,N,H*64]

// ---- packed f32x2 helpers -------------------------------------------------
__device__ __forceinline__ u64t pack2(float lo, float hi) {
    u64t r; asm("mov.b64 %0, {%1, %2};" : "=l"(r) : "f"(lo), "f"(hi)); return r;
}
__device__ __forceinline__ void unpack2(u64t v, float& lo, float& hi) {
    asm("mov.b64 {%0, %1}, %2;" : "=f"(lo), "=f"(hi) : "l"(v));
}
__device__ __forceinline__ void ffma2(u64t& d, u64t a, u64t b) {
    asm("fma.rn.f32x2 %0, %1, %2, %0;" : "+l"(d) : "l"(a), "l"(b));
}
__device__ __forceinline__ u64t fmul2(u64t a, u64t b) {
    u64t r; asm("mul.rn.f32x2 %0, %1, %2;" : "=l"(r) : "l"(a), "l"(b)); return r;
}

// ---------------------------------------------------------------------------
// Kernel 1: fused transpose + QKV projection (f32x2).
// out[n,i] = sum_c x[b,c,n] * W[i,c] + bias[i]
// A staged DUPLICATED in smem so {a,a} dup-pairs come free from LDS;
// W pairs {w0,w1} are natural consecutive floats. 8 FFMA2 per k-slice/thread.
// ---------------------------------------------------------------------------
__global__ __launch_bounds__(256) void qkv_gemm(
    const float* __restrict__ x, const float* __restrict__ Wq,
    const float* __restrict__ bq, const float* __restrict__ Wkv,
    const float* __restrict__ bkv)
{
    __shared__ __align__(16) float As2[16][136];  // [cc][2*nn] duplicated
    __shared__ __align__(16) float Ws[16][68];    // [cc][ii]

    const int b  = blockIdx.z;
    const int n0 = blockIdx.x * 64;
    const int i0 = blockIdx.y * 64;

    const float* W;  const float* bias;  int ir0;
    if (i0 < 512) { W = Wq;  bias = bq;  ir0 = i0; }
    else          { W = Wkv; bias = bkv; ir0 = i0 - 512; }

    const int tid = threadIdx.x;
    const int tx  = tid & 15;   // i micro (4 consecutive i)
    const int ty  = tid >> 4;   // n micro

    const float* xb = x + (size_t)b * NC * NN;

    u64t acc2[4][2];
#pragma unroll
    for (int un = 0; un < 4; un++) { acc2[un][0] = 0ULL; acc2[un][1] = 0ULL; }

    const int lac = tid >> 4, lan = tid & 15;  // A load
    const int lwi = tid >> 2, lwc = tid & 3;   // W load

    for (int c0 = 0; c0 < NC; c0 += 16) {
        float4 av = *(const float4*)(xb + (size_t)(c0 + lac) * NN + n0 + lan * 4);
        float4 wv = *(const float4*)(W + (size_t)(ir0 + lwi) * NC + c0 + lwc * 4);
        __syncthreads();
        // duplicated store: {x,x,y,y,z,z,w,w}
        *(float4*)&As2[lac][lan * 8 + 0] = make_float4(av.x, av.x, av.y, av.y);
        *(float4*)&As2[lac][lan * 8 + 4] = make_float4(av.z, av.z, av.w, av.w);
        Ws[lwc * 4 + 0][lwi] = wv.x;
        Ws[lwc * 4 + 1][lwi] = wv.y;
        Ws[lwc * 4 + 2][lwi] = wv.z;
        Ws[lwc * 4 + 3][lwi] = wv.w;
        __syncthreads();
#pragma unroll
        for (int cc = 0; cc < 16; cc++) {
            ulonglong2 a01 = *(const ulonglong2*)&As2[cc][ty * 8];     // dup un0, un1
            ulonglong2 a23 = *(const ulonglong2*)&As2[cc][ty * 8 + 4]; // dup un2, un3
            ulonglong2 w2  = *(const ulonglong2*)&Ws[cc][tx * 4];      // (w0,w1),(w2,w3)
            ffma2(acc2[0][0], a01.x, w2.x); ffma2(acc2[0][1], a01.x, w2.y);
            ffma2(acc2[1][0], a01.y, w2.x); ffma2(acc2[1][1], a01.y, w2.y);
            ffma2(acc2[2][0], a23.x, w2.x); ffma2(acc2[2][1], a23.x, w2.y);
            ffma2(acc2[3][0], a23.y, w2.x); ffma2(acc2[3][1], a23.y, w2.y);
        }
    }

    const int ig0 = i0 + tx * 4;
    float bs[4];
#pragma unroll
    for (int ui = 0; ui < 4; ui++) bs[ui] = bias[ir0 + tx * 4 + ui];

    float* dbase;
    int hh, dd;
    if (ig0 < 512) { dbase = g_q; hh = ig0 >> 6; dd = ig0 & 63; }
    else {
        int j0 = ig0 - 512;
        dbase = (j0 < 512) ? g_k : g_v;
        int jj = j0 & 511; hh = jj >> 6; dd = jj & 63;
    }
#pragma unroll
    for (int un = 0; un < 4; un++) {
        int n = n0 + ty * 4 + un;
        float c0f, c1f, c2f, c3f;
        unpack2(acc2[un][0], c0f, c1f);
        unpack2(acc2[un][1], c2f, c3f);
        float4 ov = make_float4(c0f + bs[0], c1f + bs[1], c2f + bs[2], c3f + bs[3]);
        *(float4*)(dbase + ((((size_t)b * NH + hh) * NN + n) * DK + dd)) = ov;
    }
}

// ---------------------------------------------------------------------------
// Kernel 2: attention, flash-style online softmax (f32x2).
// One thread = one query row. QK pairs free (natural dim pairs), PV needs one
// {p,p} pack per key. grid: (N/128, B*H), block 128.
// ---------------------------------------------------------------------------
__global__ __launch_bounds__(128) void attn_kernel()
{
    __shared__ __align__(16) float Ks[32][64];
    __shared__ __align__(16) float Vs[32][64];
    __shared__ float Ss[128][33];

    const int bh  = blockIdx.y;
    const int tid = threadIdx.x;
    const int r   = blockIdx.x * 128 + tid;

    const ulonglong2* q16 = (const ulonglong2*)(g_q + ((size_t)bh * NN + r) * DK);
    u64t q2[32];
#pragma unroll
    for (int i = 0; i < 16; i++) {
        ulonglong2 t = q16[i];
        q2[i * 2] = t.x; q2[i * 2 + 1] = t.y;
    }

    u64t o2[32];
#pragma unroll
    for (int i = 0; i < 32; i++) o2[i] = 0ULL;
    float m = -1e30f, l = 0.f;

    const float4* kb4 = (const float4*)(g_k + (size_t)bh * NN * DK);
    const float4* vb4 = (const float4*)(g_v + (size_t)bh * NN * DK);

    for (int jt = 0; jt < NN / 32; jt++) {
        int base4 = jt * 32 * 16;
#pragma unroll
        for (int u = 0; u < 4; u++) {
            int idx = tid + u * 128;
            ((float4*)Ks)[idx] = kb4[base4 + idx];
            ((float4*)Vs)[idx] = vb4[base4 + idx];
        }
        __syncthreads();

        // pass 1: scores + tile max
        float tmax = -1e30f;
#pragma unroll 8
        for (int j = 0; j < 32; j++) {
            u64t s0 = 0ULL, s1 = 0ULL, s2 = 0ULL, s3 = 0ULL;
#pragma unroll
            for (int d8 = 0; d8 < 8; d8++) {
                ulonglong2 kv = *(const ulonglong2*)&Ks[j][d8 * 8];
                ulonglong2 kw = *(const ulonglong2*)&Ks[j][d8 * 8 + 4];
                ffma2(s0, q2[d8 * 4 + 0], kv.x);
                ffma2(s1, q2[d8 * 4 + 1], kv.y);
                ffma2(s2, q2[d8 * 4 + 2], kw.x);
                ffma2(s3, q2[d8 * 4 + 3], kw.y);
            }
            float a0, a1, a2, a3, a4, a5, a6, a7;
            unpack2(s0, a0, a1); unpack2(s1, a2, a3);
            unpack2(s2, a4, a5); unpack2(s3, a6, a7);
            float sv = (((a0 + a1) + (a2 + a3)) + ((a4 + a5) + (a6 + a7))) * SCALE;
            Ss[tid][j] = sv;
            tmax = fmaxf(tmax, sv);
        }

        float mnew = fmaxf(m, tmax);
        float corr = __expf(m - mnew);
        l *= corr;
        u64t cc2 = pack2(corr, corr);
#pragma unroll
        for (int i = 0; i < 32; i++) o2[i] = fmul2(o2[i], cc2);

        // pass 2: exp + accumulate O
#pragma unroll 8
        for (int j = 0; j < 32; j++) {
            float p = __expf(Ss[tid][j] - mnew);
            l += p;
            u64t pp = pack2(p, p);
#pragma unroll
            for (int d8 = 0; d8 < 8; d8++) {
                ulonglong2 vv = *(const ulonglong2*)&Vs[j][d8 * 8];
                ulonglong2 vw = *(const ulonglong2*)&Vs[j][d8 * 8 + 4];
                ffma2(o2[d8 * 4 + 0], pp, vv.x);
                ffma2(o2[d8 * 4 + 1], pp, vv.y);
                ffma2(o2[d8 * 4 + 2], pp, vw.x);
                ffma2(o2[d8 * 4 + 3], pp, vw.y);
            }
        }
        m = mnew;
        __syncthreads();
    }

    const float inv = 1.f / l;
    const u64t inv2 = pack2(inv, inv);
    const int b = bh >> 3, h = bh & 7;
    ulonglong2* dst = (ulonglong2*)(g_mid + ((size_t)b * NN + r) * 512 + h * DK);
#pragma unroll
    for (int i = 0; i < 16; i++) {
        ulonglong2 t;
        t.x = fmul2(o2[i * 2], inv2);
        t.y = fmul2(o2[i * 2 + 1], inv2);
        dst[i] = t;
    }
}

// ---------------------------------------------------------------------------
// Kernel 3: output projection (f32x2). out[b,n,c] = sum_i mid[b,n,i]*Wp[c,i]+bp
// ---------------------------------------------------------------------------
__global__ __launch_bounds__(256) void out_gemm(
    const float* __restrict__ Wp, const float* __restrict__ bp,
    float* __restrict__ out)
{
    __shared__ __align__(16) float As2[16][136];  // [ii][2*nn] duplicated
    __shared__ __align__(16) float Ws[16][68];    // [ii][cc]

    const int b  = blockIdx.z;
    const int n0 = blockIdx.x * 64;
    const int c0 = blockIdx.y * 64;
    const int tid = threadIdx.x;
    const int tx = tid & 15;   // c micro
    const int ty = tid >> 4;   // n micro

    const float* mb = g_mid + (size_t)b * NN * 512;

    u64t acc2[4][2];
#pragma unroll
    for (int un = 0; un < 4; un++) { acc2[un][0] = 0ULL; acc2[un][1] = 0ULL; }

    const int lrow = tid >> 2, lic = tid & 3;

    for (int i0 = 0; i0 < 512; i0 += 16) {
        float4 av = *(const float4*)(mb + (size_t)(n0 + lrow) * 512 + i0 + lic * 4);
        float4 wv = *(const float4*)(Wp + (size_t)(c0 + lrow) * 512 + i0 + lic * 4);
        __syncthreads();
        *(float2*)&As2[lic * 4 + 0][lrow * 2] = make_float2(av.x, av.x);
        *(float2*)&As2[lic * 4 + 1][lrow * 2] = make_float2(av.y, av.y);
        *(float2*)&As2[lic * 4 + 2][lrow * 2] = make_float2(av.z, av.z);
        *(float2*)&As2[lic * 4 + 3][lrow * 2] = make_float2(av.w, av.w);
        Ws[lic * 4 + 0][lrow] = wv.x;
        Ws[lic * 4 + 1][lrow] = wv.y;
        Ws[lic * 4 + 2][lrow] = wv.z;
        Ws[lic * 4 + 3][lrow] = wv.w;
        __syncthreads();
#pragma unroll
        for (int cc = 0; cc < 16; cc++) {
            ulonglong2 a01 = *(const ulonglong2*)&As2[cc][ty * 8];
            ulonglong2 a23 = *(const ulonglong2*)&As2[cc][ty * 8 + 4];
            ulonglong2 w2  = *(const ulonglong2*)&Ws[cc][tx * 4];
            ffma2(acc2[0][0], a01.x, w2.x); ffma2(acc2[0][1], a01.x, w2.y);
            ffma2(acc2[1][0], a01.y, w2.x); ffma2(acc2[1][1], a01.y, w2.y);
            ffma2(acc2[2][0], a23.x, w2.x); ffma2(acc2[2][1], a23.x, w2.y);
            ffma2(acc2[3][0], a23.y, w2.x); ffma2(acc2[3][1], a23.y, w2.y);
        }
    }

    float bs[4];
#pragma unroll
    for (int ui = 0; ui < 4; ui++) bs[ui] = bp[c0 + tx * 4 + ui];
#pragma unroll
    for (int un = 0; un < 4; un++) {
        int n = n0 + ty * 4 + un;
        float c0f, c1f, c2f, c3f;
        unpack2(acc2[un][0], c0f, c1f);
        unpack2(acc2[un][1], c2f, c3f);
        float4 ov = make_float4(c0f + bs[0], c1f + bs[1], c2f + bs[2], c3f + bs[3]);
        *(float4*)(out + ((size_t)b * NN + n) * 512 + c0 + tx * 4) = ov;
    }
}

// ---------------------------------------------------------------------------
// Inputs: x, y, Wq, bq, Wkv, bkv, Wp, bp.  y unused. Output fp32 [B,N,C] flat.
// ---------------------------------------------------------------------------
extern "C" void kernel_launch(void* const* d_in, const int* in_sizes, int n_in,
                              void* d_out, int out_size)
{
    const float* x   = (const float*)d_in[0];
    const float* Wq  = (const float*)d_in[2];
    const float* bq  = (const float*)d_in[3];
    const float* Wkv = (const float*)d_in[4];
    const float* bkv = (const float*)d_in[5];
    const float* Wp  = (const float*)d_in[6];
    const float* bp  = (const float*)d_in[7];
    float* out = (float*)d_out;

    qkv_gemm<<<dim3(NN / 64, ITOT / 64, NB), 256>>>(x, Wq, bq, Wkv, bkv);
    attn_kernel<<<dim3(NN / 128, NB * NH), 128>>>();
    out_gemm<<<dim3(NN / 64, 512 / 64, NB), 256>>>(Wp, bp, out);
}

// round 4
// speedup vs baseline: 3.0840x; 3.0840x over previous
#include <cuda_runtime.h>

// B=8, C=512, H=W=32 -> N=1024 tokens, 8 heads, d_k=64, inner=512
#define NB 8
#define NC 512
#define NN 1024
#define NH 8
#define DK 64

// Scratch (device globals; allocation-free rule)
static __device__ __align__(16) float g_q[(size_t)NB * NH * NN * DK];   // [B,H,N,64]
static __device__ __align__(16) float g_k[(size_t)NB * NH * NN * DK];
static __device__ __align__(16) float g_v[(size_t)NB * NH * NN * DK];
static __device__ __align__(16) float g_mid[(size_t)NB * NN * 512];     // [B,N,H*64]

// ---- tf32 helpers ---------------------------------------------------------
__device__ __forceinline__ unsigned f2tf(float f) {
    unsigned r; asm("cvt.rna.tf32.f32 %0, %1;" : "=r"(r) : "f"(f)); return r;
}
// D(16x8) += A(16x8) * B(8x8), tf32 in, fp32 accum.
__device__ __forceinline__ void mma8(float* d, const unsigned* a,
                                     unsigned b0, unsigned b1) {
    asm("mma.sync.aligned.m16n8k8.row.col.f32.tf32.tf32.f32 "
        "{%0,%1,%2,%3},{%4,%5,%6,%7},{%8,%9},{%0,%1,%2,%3};"
        : "+f"(d[0]), "+f"(d[1]), "+f"(d[2]), "+f"(d[3])
        : "r"(a[0]), "r"(a[1]), "r"(a[2]), "r"(a[3]), "r"(b0), "r"(b1));
}

// ---------------------------------------------------------------------------
// Kernel 1: fused transpose + QKV projection via tf32 mma.
// out[n,i] = sum_c x[b,c,n]*W[i,c] + bias[i].
// Block 128n x 64i, 8 warps (4x2), warp 32x32 = 2x4 m16n8k8 atoms, k-tile 32.
// ---------------------------------------------------------------------------
__global__ __launch_bounds__(256) void qkv_gemm(
    const float* __restrict__ x, const float* __restrict__ Wq,
    const float* __restrict__ bq, const float* __restrict__ Wkv,
    const float* __restrict__ bkv)
{
    __shared__ unsigned As[32][136];  // [c][n] tf32, stride%32==8
    __shared__ unsigned Bs[32][72];   // [c][i] tf32, stride%32==8

    const int b = blockIdx.z, n0 = blockIdx.x * 128, i0 = blockIdx.y * 64;
    const float* W; const float* bias; int ir0;
    if (i0 < 512) { W = Wq;  bias = bq;  ir0 = i0; }
    else          { W = Wkv; bias = bkv; ir0 = i0 - 512; }

    const int tid = threadIdx.x, w = tid >> 5, lane = tid & 31;
    const int g = lane >> 2, tig = lane & 3;
    const int wm = w & 3, wn = w >> 2;
    const float* xb = x + (size_t)b * NC * NN;

    float acc[2][4][4];
#pragma unroll
    for (int an = 0; an < 4; an++) {
        float bv0 = bias[ir0 + wn * 32 + an * 8 + 2 * tig];
        float bv1 = bias[ir0 + wn * 32 + an * 8 + 2 * tig + 1];
#pragma unroll
        for (int am = 0; am < 2; am++) {
            acc[am][an][0] = bv0; acc[am][an][1] = bv1;
            acc[am][an][2] = bv0; acc[am][an][3] = bv1;
        }
    }

    for (int c0 = 0; c0 < NC; c0 += 32) {
        // A tile: 32 c-rows x 128 n-cols = 1024 float4 -> 4 per thread
        float4 av[4];
#pragma unroll
        for (int u = 0; u < 4; u++) {
            int idx = tid + u * 256, ar = idx >> 5, ac4 = idx & 31;
            av[u] = *(const float4*)(xb + (size_t)(c0 + ar) * NN + n0 + ac4 * 4);
        }
        // B tile: 64 i-rows x 32 c-cols = 512 float4 -> 2 per thread
        float4 wv[2];
#pragma unroll
        for (int u = 0; u < 2; u++) {
            int idx = tid + u * 256, br = idx >> 3, bc4 = idx & 7;
            wv[u] = *(const float4*)(W + (size_t)(ir0 + br) * NC + c0 + bc4 * 4);
        }
        __syncthreads();
#pragma unroll
        for (int u = 0; u < 4; u++) {
            int idx = tid + u * 256, ar = idx >> 5, ac4 = idx & 31;
            uint4 at;
            at.x = f2tf(av[u].x); at.y = f2tf(av[u].y);
            at.z = f2tf(av[u].z); at.w = f2tf(av[u].w);
            *(uint4*)&As[ar][ac4 * 4] = at;
        }
#pragma unroll
        for (int u = 0; u < 2; u++) {
            int idx = tid + u * 256, br = idx >> 3, bc4 = idx & 7;
            Bs[bc4 * 4 + 0][br] = f2tf(wv[u].x);
            Bs[bc4 * 4 + 1][br] = f2tf(wv[u].y);
            Bs[bc4 * 4 + 2][br] = f2tf(wv[u].z);
            Bs[bc4 * 4 + 3][br] = f2tf(wv[u].w);
        }
        __syncthreads();
#pragma unroll
        for (int ks = 0; ks < 4; ks++) {
            const int kb = ks * 8;
            unsigned a[2][4];
#pragma unroll
            for (int am = 0; am < 2; am++) {
                int nb = wm * 32 + am * 16;
                a[am][0] = As[kb + tig][nb + g];
                a[am][1] = As[kb + tig][nb + 8 + g];
                a[am][2] = As[kb + tig + 4][nb + g];
                a[am][3] = As[kb + tig + 4][nb + 8 + g];
            }
#pragma unroll
            for (int an = 0; an < 4; an++) {
                unsigned b0 = Bs[kb + tig][wn * 32 + an * 8 + g];
                unsigned b1 = Bs[kb + tig + 4][wn * 32 + an * 8 + g];
                mma8(acc[0][an], a[0], b0, b1);
                mma8(acc[1][an], a[1], b0, b1);
            }
        }
    }

    float* dbase; int rel;
    if (i0 < 512)       { dbase = g_q; rel = i0; }
    else if (i0 < 1024) { dbase = g_k; rel = i0 - 512; }
    else                { dbase = g_v; rel = i0 - 1024; }
    const int hh = rel >> 6;
    float* hbase = dbase + (((size_t)b * NH + hh) * NN) * DK;
#pragma unroll
    for (int am = 0; am < 2; am++) {
        int r0 = n0 + wm * 32 + am * 16 + g;
#pragma unroll
        for (int an = 0; an < 4; an++) {
            int dd = wn * 32 + an * 8 + 2 * tig;
            *(float2*)(hbase + (size_t)r0 * DK + dd) =
                make_float2(acc[am][an][0], acc[am][an][1]);
            *(float2*)(hbase + (size_t)(r0 + 8) * DK + dd) =
                make_float2(acc[am][an][2], acc[am][an][3]);
        }
    }
}

// ---------------------------------------------------------------------------
// Kernel 2: attention via tf32 mma, flash-style online softmax.
// Block: 128 q rows, 8 warps (16 q rows each), 32-key tiles, full d=64.
// ---------------------------------------------------------------------------
__global__ __launch_bounds__(256) void attn_kernel()
{
    __shared__ unsigned Ks[32][68];    // [key][d]  stride%32==4
    __shared__ unsigned Vs[32][72];    // [key][d]  stride%32==8
    __shared__ unsigned Ps[128][36];   // [q][key]  stride%32==4

    const int bh = blockIdx.y, q0 = blockIdx.x * 128;
    const int tid = threadIdx.x, w = tid >> 5, lane = tid & 31;
    const int g = lane >> 2, tig = lane & 3;

    // Q fragments (A operand), pre-scaled by 1/8 (exact power of 2)
    const float* Qb = g_q + ((size_t)bh * NN + q0 + w * 16) * DK;
    unsigned qf[8][4];
#pragma unroll
    for (int s = 0; s < 8; s++) {
        qf[s][0] = f2tf(Qb[(size_t)g * DK + s * 8 + tig] * 0.125f);
        qf[s][1] = f2tf(Qb[(size_t)(g + 8) * DK + s * 8 + tig] * 0.125f);
        qf[s][2] = f2tf(Qb[(size_t)g * DK + s * 8 + tig + 4] * 0.125f);
        qf[s][3] = f2tf(Qb[(size_t)(g + 8) * DK + s * 8 + tig + 4] * 0.125f);
    }

    float o[8][4];
#pragma unroll
    for (int an = 0; an < 8; an++)
        o[an][0] = o[an][1] = o[an][2] = o[an][3] = 0.f;
    float m0 = -1e30f, m1 = -1e30f, l0 = 0.f, l1 = 0.f;

    const float4* Kb4 = (const float4*)(g_k + (size_t)bh * NN * DK);
    const float4* Vb4 = (const float4*)(g_v + (size_t)bh * NN * DK);

    for (int jt = 0; jt < 32; jt++) {
        const int base4 = jt * 32 * 16;
        float4 k0v = Kb4[base4 + tid], k1v = Kb4[base4 + tid + 256];
        float4 v0v = Vb4[base4 + tid], v1v = Vb4[base4 + tid + 256];
        __syncthreads();
        {
            int r = tid >> 4, c4 = tid & 15;
            uint4 t;
            t.x = f2tf(k0v.x); t.y = f2tf(k0v.y); t.z = f2tf(k0v.z); t.w = f2tf(k0v.w);
            *(uint4*)&Ks[r][c4 * 4] = t;
            t.x = f2tf(v0v.x); t.y = f2tf(v0v.y); t.z = f2tf(v0v.z); t.w = f2tf(v0v.w);
            *(uint4*)&Vs[r][c4 * 4] = t;
            t.x = f2tf(k1v.x); t.y = f2tf(k1v.y); t.z = f2tf(k1v.z); t.w = f2tf(k1v.w);
            *(uint4*)&Ks[r + 16][c4 * 4] = t;
            t.x = f2tf(v1v.x); t.y = f2tf(v1v.y); t.z = f2tf(v1v.z); t.w = f2tf(v1v.w);
            *(uint4*)&Vs[r + 16][c4 * 4] = t;
        }
        __syncthreads();

        // S = Q K^T
        float s[4][4];
#pragma unroll
        for (int an = 0; an < 4; an++)
            s[an][0] = s[an][1] = s[an][2] = s[an][3] = 0.f;
#pragma unroll
        for (int ks = 0; ks < 8; ks++) {
#pragma unroll
            for (int an = 0; an < 4; an++) {
                unsigned b0 = Ks[an * 8 + g][ks * 8 + tig];
                unsigned b1 = Ks[an * 8 + g][ks * 8 + tig + 4];
                mma8(s[an], qf[ks], b0, b1);
            }
        }

        // online softmax (rows g and g+8)
        float tm0 = -1e30f, tm1 = -1e30f;
#pragma unroll
        for (int an = 0; an < 4; an++) {
            tm0 = fmaxf(tm0, fmaxf(s[an][0], s[an][1]));
            tm1 = fmaxf(tm1, fmaxf(s[an][2], s[an][3]));
        }
        tm0 = fmaxf(tm0, __shfl_xor_sync(0xffffffffu, tm0, 1));
        tm0 = fmaxf(tm0, __shfl_xor_sync(0xffffffffu, tm0, 2));
        tm1 = fmaxf(tm1, __shfl_xor_sync(0xffffffffu, tm1, 1));
        tm1 = fmaxf(tm1, __shfl_xor_sync(0xffffffffu, tm1, 2));
        float mn0 = fmaxf(m0, tm0), mn1 = fmaxf(m1, tm1);
        float corr0 = __expf(m0 - mn0), corr1 = __expf(m1 - mn1);
        m0 = mn0; m1 = mn1;

        float ps0 = 0.f, ps1 = 0.f;
#pragma unroll
        for (int an = 0; an < 4; an++) {
            float p0 = __expf(s[an][0] - mn0);
            float p1 = __expf(s[an][1] - mn0);
            float p2 = __expf(s[an][2] - mn1);
            float p3 = __expf(s[an][3] - mn1);
            ps0 += p0 + p1; ps1 += p2 + p3;
            uint2 t0; t0.x = f2tf(p0); t0.y = f2tf(p1);
            *(uint2*)&Ps[w * 16 + g][an * 8 + 2 * tig] = t0;
            uint2 t1; t1.x = f2tf(p2); t1.y = f2tf(p3);
            *(uint2*)&Ps[w * 16 + 8 + g][an * 8 + 2 * tig] = t1;
        }
        l0 = l0 * corr0 + ps0;
        l1 = l1 * corr1 + ps1;
#pragma unroll
        for (int an = 0; an < 8; an++) {
            o[an][0] *= corr0; o[an][1] *= corr0;
            o[an][2] *= corr1; o[an][3] *= corr1;
        }
        __syncwarp();

        // O += P V
#pragma unroll
        for (int ks = 0; ks < 4; ks++) {
            unsigned pa[4];
            pa[0] = Ps[w * 16 + g][ks * 8 + tig];
            pa[1] = Ps[w * 16 + 8 + g][ks * 8 + tig];
            pa[2] = Ps[w * 16 + g][ks * 8 + tig + 4];
            pa[3] = Ps[w * 16 + 8 + g][ks * 8 + tig + 4];
#pragma unroll
            for (int an = 0; an < 8; an++) {
                unsigned b0 = Vs[ks * 8 + tig][an * 8 + g];
                unsigned b1 = Vs[ks * 8 + tig + 4][an * 8 + g];
                mma8(o[an], pa, b0, b1);
            }
        }
        __syncwarp();
    }

    l0 += __shfl_xor_sync(0xffffffffu, l0, 1);
    l0 += __shfl_xor_sync(0xffffffffu, l0, 2);
    l1 += __shfl_xor_sync(0xffffffffu, l1, 1);
    l1 += __shfl_xor_sync(0xffffffffu, l1, 2);
    const float inv0 = 1.f / l0, inv1 = 1.f / l1;

    const int bb = bh >> 3, h = bh & 7;
    float* dst = g_mid + ((size_t)bb * NN + q0 + w * 16) * 512 + h * 64;
#pragma unroll
    for (int an = 0; an < 8; an++) {
        int dd = an * 8 + 2 * tig;
        *(float2*)(dst + (size_t)g * 512 + dd) =
            make_float2(o[an][0] * inv0, o[an][1] * inv0);
        *(float2*)(dst + (size_t)(g + 8) * 512 + dd) =
            make_float2(o[an][2] * inv1, o[an][3] * inv1);
    }
}

// ---------------------------------------------------------------------------
// Kernel 3: output projection via tf32 mma.
// ---------------------------------------------------------------------------
__global__ __launch_bounds__(256) void out_gemm(
    const float* __restrict__ Wp, const float* __restrict__ bp,
    float* __restrict__ out)
{
    __shared__ unsigned As[32][136];  // [i][n]
    __shared__ unsigned Bs[32][72];   // [i][c]

    const int b = blockIdx.z, n0 = blockIdx.x * 128, c0b = blockIdx.y * 64;
    const int tid = threadIdx.x, w = tid >> 5, lane = tid & 31;
    const int g = lane >> 2, tig = lane & 3;
    const int wm = w & 3, wn = w >> 2;
    const float* mb = g_mid + (size_t)b * NN * 512;

    float acc[2][4][4];
#pragma unroll
    for (int an = 0; an < 4; an++) {
        float bv0 = bp[c0b + wn * 32 + an * 8 + 2 * tig];
        float bv1 = bp[c0b + wn * 32 + an * 8 + 2 * tig + 1];
#pragma unroll
        for (int am = 0; am < 2; am++) {
            acc[am][an][0] = bv0; acc[am][an][1] = bv1;
            acc[am][an][2] = bv0; acc[am][an][3] = bv1;
        }
    }

    for (int i0 = 0; i0 < 512; i0 += 32) {
        float4 av[4];
#pragma unroll
        for (int u = 0; u < 4; u++) {
            int idx = tid + u * 256, r = idx >> 3, c4 = idx & 7;
            av[u] = *(const float4*)(mb + (size_t)(n0 + r) * 512 + i0 + c4 * 4);
        }
        float4 wv[2];
#pragma unroll
        for (int u = 0; u < 2; u++) {
            int idx = tid + u * 256, cr = idx >> 3, c4 = idx & 7;
            wv[u] = *(const float4*)(Wp + (size_t)(c0b + cr) * 512 + i0 + c4 * 4);
        }
        __syncthreads();
#pragma unroll
        for (int u = 0; u < 4; u++) {
            int idx = tid + u * 256, r = idx >> 3, c4 = idx & 7;
            As[c4 * 4 + 0][r] = f2tf(av[u].x);
            As[c4 * 4 + 1][r] = f2tf(av[u].y);
            As[c4 * 4 + 2][r] = f2tf(av[u].z);
            As[c4 * 4 + 3][r] = f2tf(av[u].w);
        }
#pragma unroll
        for (int u = 0; u < 2; u++) {
            int idx = tid + u * 256, cr = idx >> 3, c4 = idx & 7;
            Bs[c4 * 4 + 0][cr] = f2tf(wv[u].x);
            Bs[c4 * 4 + 1][cr] = f2tf(wv[u].y);
            Bs[c4 * 4 + 2][cr] = f2tf(wv[u].z);
            Bs[c4 * 4 + 3][cr] = f2tf(wv[u].w);
        }
        __syncthreads();
#pragma unroll
        for (int ks = 0; ks < 4; ks++) {
            const int kb = ks * 8;
            unsigned a[2][4];
#pragma unroll
            for (int am = 0; am < 2; am++) {
                int nb = wm * 32 + am * 16;
                a[am][0] = As[kb + tig][nb + g];
                a[am][1] = As[kb + tig][nb + 8 + g];
                a[am][2] = As[kb + tig + 4][nb + g];
                a[am][3] = As[kb + tig + 4][nb + 8 + g];
            }
#pragma unroll
            for (int an = 0; an < 4; an++) {
                unsigned b0 = Bs[kb + tig][wn * 32 + an * 8 + g];
                unsigned b1 = Bs[kb + tig + 4][wn * 32 + an * 8 + g];
                mma8(acc[0][an], a[0], b0, b1);
                mma8(acc[1][an], a[1], b0, b1);
            }
        }
    }

#pragma unroll
    for (int am = 0; am < 2; am++) {
        int r0 = n0 + wm * 32 + am * 16 + g;
#pragma unroll
        for (int an = 0; an < 4; an++) {
            int cc = c0b + wn * 32 + an * 8 + 2 * tig;
            *(float2*)(out + ((size_t)b * NN + r0) * 512 + cc) =
                make_float2(acc[am][an][0], acc[am][an][1]);
            *(float2*)(out + ((size_t)b * NN + r0 + 8) * 512 + cc) =
                make_float2(acc[am][an][2], acc[am][an][3]);
        }
    }
}

// ---------------------------------------------------------------------------
// Inputs: x, y, Wq, bq, Wkv, bkv, Wp, bp.  y unused. Output fp32 [B,N,C] flat.
// ---------------------------------------------------------------------------
extern "C" void kernel_launch(void* const* d_in, const int* in_sizes, int n_in,
                              void* d_out, int out_size)
{
    const float* x   = (const float*)d_in[0];
    const float* Wq  = (const float*)d_in[2];
    const float* bq  = (const float*)d_in[3];
    const float* Wkv = (const float*)d_in[4];
    const float* bkv = (const float*)d_in[5];
    const float* Wp  = (const float*)d_in[6];
    const float* bp  = (const float*)d_in[7];
    float* out = (float*)d_out;

    qkv_gemm<<<dim3(NN / 128, 1536 / 64, NB), 256>>>(x, Wq, bq, Wkv, bkv);
    attn_kernel<<<dim3(NN / 128, NB * NH), 256>>>();
    out_gemm<<<dim3(NN / 128, 512 / 64, NB), 256>>>(Wp, bp, out);
}

// round 5
// speedup vs baseline: 4.2421x; 1.3755x over previous
#include <cuda_runtime.h>

// B=8, C=512, H=W=32 -> N=1024 tokens, 8 heads, d_k=64, inner=512
#define NB 8
#define NC 512
#define NN 1024
#define NH 8
#define DK 64

// Scratch (device globals; allocation-free rule)
static __device__ __align__(16) float g_q[(size_t)NB * NH * NN * DK];   // [B,H,N,64]
static __device__ __align__(16) float g_k[(size_t)NB * NH * NN * DK];
static __device__ __align__(16) float g_v[(size_t)NB * NH * NN * DK];
static __device__ __align__(16) float g_mid[(size_t)NB * NN * 512];     // [B,N,H*64]

// ---- tf32 helpers ---------------------------------------------------------
__device__ __forceinline__ unsigned f2tf(float f) {
    unsigned r; asm("cvt.rna.tf32.f32 %0, %1;" : "=r"(r) : "f"(f)); return r;
}
__device__ __forceinline__ uint4 cvt4(float4 v) {
    uint4 t; t.x = f2tf(v.x); t.y = f2tf(v.y); t.z = f2tf(v.z); t.w = f2tf(v.w);
    return t;
}
// D(16x8) += A(16x8) * B(8x8), tf32 in, fp32 accum.
__device__ __forceinline__ void mma8(float* d, const unsigned* a,
                                     unsigned b0, unsigned b1) {
    asm("mma.sync.aligned.m16n8k8.row.col.f32.tf32.tf32.f32 "
        "{%0,%1,%2,%3},{%4,%5,%6,%7},{%8,%9},{%0,%1,%2,%3};"
        : "+f"(d[0]), "+f"(d[1]), "+f"(d[2]), "+f"(d[3])
        : "r"(a[0]), "r"(a[1]), "r"(a[2]), "r"(a[3]), "r"(b0), "r"(b1));
}

// ---------------------------------------------------------------------------
// Kernel 1: fused transpose + QKV projection, tf32 mma, transpose-free smem.
// M = i (weight rows), N = n (tokens): A = W[i][c] ([m][k] as stored),
// B = x[c][n] ([k][n] as stored). Block 128i x 128n, 8 warps (2m x 4n),
// warp 64x32 (4x4 atoms), k-tile 32, register prefetch of next k-tile.
// ---------------------------------------------------------------------------
__global__ __launch_bounds__(256) void qkv_gemm(
    const float* __restrict__ x, const float* __restrict__ Wq,
    const float* __restrict__ bq, const float* __restrict__ Wkv,
    const float* __restrict__ bkv)
{
    __shared__ unsigned As[128][36];   // [i][c], stride%32==4
    __shared__ unsigned Bs[32][136];   // [c][n], stride%32==8

    const int b = blockIdx.z, n0 = blockIdx.x * 128, i0 = blockIdx.y * 128;
    const float* W; const float* bias; int ir0;
    if (i0 < 512) { W = Wq;  bias = bq;  ir0 = i0; }
    else          { W = Wkv; bias = bkv; ir0 = i0 - 512; }

    const int tid = threadIdx.x, w = tid >> 5, lane = tid & 31;
    const int g = lane >> 2, tig = lane & 3;
    const int wm = w & 1, wn = w >> 1;
    const float* xb = x + (size_t)b * NC * NN;

    float acc[4][4][4];
#pragma unroll
    for (int am = 0; am < 4; am++) {
        float bv0 = bias[ir0 + wm * 64 + am * 16 + g];
        float bv1 = bias[ir0 + wm * 64 + am * 16 + 8 + g];
#pragma unroll
        for (int an = 0; an < 4; an++) {
            acc[am][an][0] = bv0; acc[am][an][1] = bv0;
            acc[am][an][2] = bv1; acc[am][an][3] = bv1;
        }
    }

    const int ar = tid >> 3, ac4 = tid & 7;    // A fill: +32u rows
    const int br = tid >> 5, bc4 = tid & 31;   // B fill: +8u rows

    float4 awv[4], bxv[4];
#pragma unroll
    for (int u = 0; u < 4; u++) {
        awv[u] = *(const float4*)(W + (size_t)(ir0 + ar + 32 * u) * NC + ac4 * 4);
        bxv[u] = *(const float4*)(xb + (size_t)(br + 8 * u) * NN + n0 + bc4 * 4);
    }

    for (int c0 = 0; c0 < NC; c0 += 32) {
        __syncthreads();
#pragma unroll
        for (int u = 0; u < 4; u++) {
            *(uint4*)&As[ar + 32 * u][ac4 * 4] = cvt4(awv[u]);
            *(uint4*)&Bs[br + 8 * u][bc4 * 4] = cvt4(bxv[u]);
        }
        __syncthreads();
        if (c0 + 32 < NC) {
#pragma unroll
            for (int u = 0; u < 4; u++) {
                awv[u] = *(const float4*)(W + (size_t)(ir0 + ar + 32 * u) * NC + c0 + 32 + ac4 * 4);
                bxv[u] = *(const float4*)(xb + (size_t)(c0 + 32 + br + 8 * u) * NN + n0 + bc4 * 4);
            }
        }
#pragma unroll
        for (int ks = 0; ks < 4; ks++) {
            const int kb = ks * 8;
            unsigned a[4][4];
#pragma unroll
            for (int am = 0; am < 4; am++) {
                int mr = wm * 64 + am * 16;
                a[am][0] = As[mr + g][kb + tig];
                a[am][1] = As[mr + 8 + g][kb + tig];
                a[am][2] = As[mr + g][kb + tig + 4];
                a[am][3] = As[mr + 8 + g][kb + tig + 4];
            }
#pragma unroll
            for (int an = 0; an < 4; an++) {
                unsigned b0 = Bs[kb + tig][wn * 32 + an * 8 + g];
                unsigned b1 = Bs[kb + tig + 4][wn * 32 + an * 8 + g];
#pragma unroll
                for (int am = 0; am < 4; am++)
                    mma8(acc[am][an], a[am], b0, b1);
            }
        }
    }

    float* dbase; int rel;
    if (i0 < 512)       { dbase = g_q; rel = i0; }
    else if (i0 < 1024) { dbase = g_k; rel = i0 - 512; }
    else                { dbase = g_v; rel = i0 - 1024; }
#pragma unroll
    for (int am = 0; am < 4; am++) {
        int ri = rel + wm * 64 + am * 16 + g;
        int hh = ri >> 6, dd = ri & 63;
        float* hb = dbase + (((size_t)b * NH + hh) * NN) * DK;
#pragma unroll
        for (int an = 0; an < 4; an++) {
            int n = n0 + wn * 32 + an * 8 + 2 * tig;
            hb[(size_t)n * DK + dd]           = acc[am][an][0];
            hb[(size_t)(n + 1) * DK + dd]     = acc[am][an][1];
            hb[(size_t)n * DK + dd + 8]       = acc[am][an][2];
            hb[(size_t)(n + 1) * DK + dd + 8] = acc[am][an][3];
        }
    }
}

// ---------------------------------------------------------------------------
// Kernel 2: attention, tf32 mma, flash-style online softmax.
// Block: 128 q rows, 4 warps x 32 q rows (2 m-atoms), 32-key tiles, d=64.
// KV register prefetch overlaps LDG with mma/softmax.
// ---------------------------------------------------------------------------
__global__ __launch_bounds__(128) void attn_kernel()
{
    __shared__ unsigned Ks[32][68];    // [key][d]  stride%32==4
    __shared__ unsigned Vs[32][72];    // [key][d]  stride%32==8
    __shared__ unsigned Ps[128][36];   // [q][key]  stride%32==4

    const int bh = blockIdx.y, q0 = blockIdx.x * 128;
    const int tid = threadIdx.x, w = tid >> 5, lane = tid & 31;
    const int g = lane >> 2, tig = lane & 3;

    // Q fragments (A operand), pre-scaled by 1/8 (exact power of 2)
    const float* Qb = g_q + ((size_t)bh * NN + q0 + w * 32) * DK;
    unsigned qf[2][8][4];
#pragma unroll
    for (int am = 0; am < 2; am++)
#pragma unroll
        for (int s = 0; s < 8; s++) {
            qf[am][s][0] = f2tf(Qb[(size_t)(am * 16 + g) * DK + s * 8 + tig] * 0.125f);
            qf[am][s][1] = f2tf(Qb[(size_t)(am * 16 + 8 + g) * DK + s * 8 + tig] * 0.125f);
            qf[am][s][2] = f2tf(Qb[(size_t)(am * 16 + g) * DK + s * 8 + tig + 4] * 0.125f);
            qf[am][s][3] = f2tf(Qb[(size_t)(am * 16 + 8 + g) * DK + s * 8 + tig + 4] * 0.125f);
        }

    float o[2][8][4];
#pragma unroll
    for (int am = 0; am < 2; am++)
#pragma unroll
        for (int an = 0; an < 8; an++)
            o[am][an][0] = o[am][an][1] = o[am][an][2] = o[am][an][3] = 0.f;
    float m[2][2] = {{-1e30f, -1e30f}, {-1e30f, -1e30f}};
    float l[2][2] = {{0.f, 0.f}, {0.f, 0.f}};

    const float4* Kb4 = (const float4*)(g_k + (size_t)bh * NN * DK);
    const float4* Vb4 = (const float4*)(g_v + (size_t)bh * NN * DK);

    float4 kr[4], vr[4];
#pragma unroll
    for (int u = 0; u < 4; u++) {
        kr[u] = Kb4[tid + u * 128];
        vr[u] = Vb4[tid + u * 128];
    }

    const int sr = tid >> 4, sc4 = tid & 15;
    for (int jt = 0; jt < 32; jt++) {
        __syncthreads();
#pragma unroll
        for (int u = 0; u < 4; u++) {
            *(uint4*)&Ks[sr + 8 * u][sc4 * 4] = cvt4(kr[u]);
            *(uint4*)&Vs[sr + 8 * u][sc4 * 4] = cvt4(vr[u]);
        }
        __syncthreads();
        if (jt < 31) {
            const int base4 = (jt + 1) * 512;
#pragma unroll
            for (int u = 0; u < 4; u++) {
                kr[u] = Kb4[base4 + tid + u * 128];
                vr[u] = Vb4[base4 + tid + u * 128];
            }
        }

        // S = Q K^T
        float s[2][4][4];
#pragma unroll
        for (int am = 0; am < 2; am++)
#pragma unroll
            for (int an = 0; an < 4; an++)
                s[am][an][0] = s[am][an][1] = s[am][an][2] = s[am][an][3] = 0.f;
#pragma unroll
        for (int ks = 0; ks < 8; ks++)
#pragma unroll
            for (int an = 0; an < 4; an++) {
                unsigned b0 = Ks[an * 8 + g][ks * 8 + tig];
                unsigned b1 = Ks[an * 8 + g][ks * 8 + tig + 4];
                mma8(s[0][an], qf[0][ks], b0, b1);
                mma8(s[1][an], qf[1][ks], b0, b1);
            }

        // online softmax per m-atom (rows g and g+8 of each 16-row atom)
#pragma unroll
        for (int am = 0; am < 2; am++) {
            float tm0 = -1e30f, tm1 = -1e30f;
#pragma unroll
            for (int an = 0; an < 4; an++) {
                tm0 = fmaxf(tm0, fmaxf(s[am][an][0], s[am][an][1]));
                tm1 = fmaxf(tm1, fmaxf(s[am][an][2], s[am][an][3]));
            }
            tm0 = fmaxf(tm0, __shfl_xor_sync(0xffffffffu, tm0, 1));
            tm0 = fmaxf(tm0, __shfl_xor_sync(0xffffffffu, tm0, 2));
            tm1 = fmaxf(tm1, __shfl_xor_sync(0xffffffffu, tm1, 1));
            tm1 = fmaxf(tm1, __shfl_xor_sync(0xffffffffu, tm1, 2));
            float mn0 = fmaxf(m[am][0], tm0), mn1 = fmaxf(m[am][1], tm1);
            float corr0 = __expf(m[am][0] - mn0), corr1 = __expf(m[am][1] - mn1);
            m[am][0] = mn0; m[am][1] = mn1;

            float ps0 = 0.f, ps1 = 0.f;
#pragma unroll
            for (int an = 0; an < 4; an++) {
                float p0 = __expf(s[am][an][0] - mn0);
                float p1 = __expf(s[am][an][1] - mn0);
                float p2 = __expf(s[am][an][2] - mn1);
                float p3 = __expf(s[am][an][3] - mn1);
                ps0 += p0 + p1; ps1 += p2 + p3;
                uint2 t0; t0.x = f2tf(p0); t0.y = f2tf(p1);
                *(uint2*)&Ps[w * 32 + am * 16 + g][an * 8 + 2 * tig] = t0;
                uint2 t1; t1.x = f2tf(p2); t1.y = f2tf(p3);
                *(uint2*)&Ps[w * 32 + am * 16 + 8 + g][an * 8 + 2 * tig] = t1;
            }
            l[am][0] = l[am][0] * corr0 + ps0;
            l[am][1] = l[am][1] * corr1 + ps1;
#pragma unroll
            for (int an = 0; an < 8; an++) {
                o[am][an][0] *= corr0; o[am][an][1] *= corr0;
                o[am][an][2] *= corr1; o[am][an][3] *= corr1;
            }
        }
        __syncwarp();

        // O += P V
#pragma unroll
        for (int ks = 0; ks < 4; ks++) {
            unsigned pa[2][4];
#pragma unroll
            for (int am = 0; am < 2; am++) {
                pa[am][0] = Ps[w * 32 + am * 16 + g][ks * 8 + tig];
                pa[am][1] = Ps[w * 32 + am * 16 + 8 + g][ks * 8 + tig];
                pa[am][2] = Ps[w * 32 + am * 16 + g][ks * 8 + tig + 4];
                pa[am][3] = Ps[w * 32 + am * 16 + 8 + g][ks * 8 + tig + 4];
            }
#pragma unroll
            for (int an = 0; an < 8; an++) {
                unsigned b0 = Vs[ks * 8 + tig][an * 8 + g];
                unsigned b1 = Vs[ks * 8 + tig + 4][an * 8 + g];
                mma8(o[0][an], pa[0], b0, b1);
                mma8(o[1][an], pa[1], b0, b1);
            }
        }
        __syncwarp();
    }

#pragma unroll
    for (int am = 0; am < 2; am++) {
        l[am][0] += __shfl_xor_sync(0xffffffffu, l[am][0], 1);
        l[am][0] += __shfl_xor_sync(0xffffffffu, l[am][0], 2);
        l[am][1] += __shfl_xor_sync(0xffffffffu, l[am][1], 1);
        l[am][1] += __shfl_xor_sync(0xffffffffu, l[am][1], 2);
    }

    const int bb = bh >> 3, h = bh & 7;
    float* dst = g_mid + ((size_t)bb * NN + q0 + w * 32) * 512 + h * 64;
#pragma unroll
    for (int am = 0; am < 2; am++) {
        float inv0 = 1.f / l[am][0], inv1 = 1.f / l[am][1];
#pragma unroll
        for (int an = 0; an < 8; an++) {
            int dd = an * 8 + 2 * tig;
            *(float2*)(dst + (size_t)(am * 16 + g) * 512 + dd) =
                make_float2(o[am][an][0] * inv0, o[am][an][1] * inv0);
            *(float2*)(dst + (size_t)(am * 16 + 8 + g) * 512 + dd) =
                make_float2(o[am][an][2] * inv1, o[am][an][3] * inv1);
        }
    }
}

// ---------------------------------------------------------------------------
// Kernel 3: output projection, tf32 mma, transpose-free smem.
// M = c (Wp rows), N = n: A = Wp[c][i] ([m][k]), B = mid[n][i] ([n][k]).
// Block 128c x 128n, warp 64x32, k-tile 32, prefetch.
// ---------------------------------------------------------------------------
__global__ __launch_bounds__(256) void out_gemm(
    const float* __restrict__ Wp, const float* __restrict__ bp,
    float* __restrict__ out)
{
    __shared__ unsigned As[128][36];   // [c][i], stride%32==4
    __shared__ unsigned Bs[128][36];   // [n][i], stride%32==4

    const int b = blockIdx.z, n0 = blockIdx.x * 128, c0 = blockIdx.y * 128;
    const int tid = threadIdx.x, w = tid >> 5, lane = tid & 31;
    const int g = lane >> 2, tig = lane & 3;
    const int wm = w & 1, wn = w >> 1;
    const float* mb = g_mid + (size_t)b * NN * 512;

    float acc[4][4][4];
#pragma unroll
    for (int am = 0; am < 4; am++) {
        float bv0 = bp[c0 + wm * 64 + am * 16 + g];
        float bv1 = bp[c0 + wm * 64 + am * 16 + 8 + g];
#pragma unroll
        for (int an = 0; an < 4; an++) {
            acc[am][an][0] = bv0; acc[am][an][1] = bv0;
            acc[am][an][2] = bv1; acc[am][an][3] = bv1;
        }
    }

    const int ar = tid >> 3, ac4 = tid & 7;

    float4 awv[4], bmv[4];
#pragma unroll
    for (int u = 0; u < 4; u++) {
        awv[u] = *(const float4*)(Wp + (size_t)(c0 + ar + 32 * u) * 512 + ac4 * 4);
        bmv[u] = *(const float4*)(mb + (size_t)(n0 + ar + 32 * u) * 512 + ac4 * 4);
    }

    for (int k0 = 0; k0 < 512; k0 += 32) {
        __syncthreads();
#pragma unroll
        for (int u = 0; u < 4; u++) {
            *(uint4*)&As[ar + 32 * u][ac4 * 4] = cvt4(awv[u]);
            *(uint4*)&Bs[ar + 32 * u][ac4 * 4] = cvt4(bmv[u]);
        }
        __syncthreads();
        if (k0 + 32 < 512) {
#pragma unroll
            for (int u = 0; u < 4; u++) {
                awv[u] = *(const float4*)(Wp + (size_t)(c0 + ar + 32 * u) * 512 + k0 + 32 + ac4 * 4);
                bmv[u] = *(const float4*)(mb + (size_t)(n0 + ar + 32 * u) * 512 + k0 + 32 + ac4 * 4);
            }
        }
#pragma unroll
        for (int ks = 0; ks < 4; ks++) {
            const int kb = ks * 8;
            unsigned a[4][4];
#pragma unroll
            for (int am = 0; am < 4; am++) {
                int mr = wm * 64 + am * 16;
                a[am][0] = As[mr + g][kb + tig];
                a[am][1] = As[mr + 8 + g][kb + tig];
                a[am][2] = As[mr + g][kb + tig + 4];
                a[am][3] = As[mr + 8 + g][kb + tig + 4];
            }
#pragma unroll
            for (int an = 0; an < 4; an++) {
                unsigned b0 = Bs[wn * 32 + an * 8 + g][kb + tig];
                unsigned b1 = Bs[wn * 32 + an * 8 + g][kb + tig + 4];
#pragma unroll
                for (int am = 0; am < 4; am++)
                    mma8(acc[am][an], a[am], b0, b1);
            }
        }
    }

#pragma unroll
    for (int am = 0; am < 4; am++) {
        int cc = c0 + wm * 64 + am * 16 + g;
#pragma unroll
        for (int an = 0; an < 4; an++) {
            int n = n0 + wn * 32 + an * 8 + 2 * tig;
            out[((size_t)b * NN + n) * 512 + cc]         = acc[am][an][0];
            out[((size_t)b * NN + n + 1) * 512 + cc]     = acc[am][an][1];
            out[((size_t)b * NN + n) * 512 + cc + 8]     = acc[am][an][2];
            out[((size_t)b * NN + n + 1) * 512 + cc + 8] = acc[am][an][3];
        }
    }
}

// ---------------------------------------------------------------------------
// Inputs: x, y, Wq, bq, Wkv, bkv, Wp, bp.  y unused. Output fp32 [B,N,C] flat.
// ---------------------------------------------------------------------------
extern "C" void kernel_launch(void* const* d_in, const int* in_sizes, int n_in,
                              void* d_out, int out_size)
{
    const float* x   = (const float*)d_in[0];
    const float* Wq  = (const float*)d_in[2];
    const float* bq  = (const float*)d_in[3];
    const float* Wkv = (const float*)d_in[4];
    const float* bkv = (const float*)d_in[5];
    const float* Wp  = (const float*)d_in[6];
    const float* bp  = (const float*)d_in[7];
    float* out = (float*)d_out;

    qkv_gemm<<<dim3(NN / 128, 1536 / 128, NB), 256>>>(x, Wq, bq, Wkv, bkv);
    attn_kernel<<<dim3(NN / 128, NB * NH), 128>>>();
    out_gemm<<<dim3(NN / 128, 512 / 128, NB), 256>>>(Wp, bp, out);
}